// round 13
// baseline (speedup 1.0000x reference)
#include <cuda_runtime.h>

// Trilinear interpolation:
//   img:    [64, 64, 64, 64]  (D, H, W, C) fp32, C contiguous
//   coords: [200000, 3] fp32 in [0, 128)  -> scaled by 1/2 into [0, 64)
//   out:    [200000, 64] fp32
//
// Half-warp per point: lanes 0-15 -> point 2w, lanes 16-31 -> point 2w+1.
// Each lane covers 4 channels (float4). 8 corner loads per lane, all
// front-batched (8-deep MLP vs 4 previously), 32 FMAs, no shuffles, one
// dense full-warp STG.128 (2 adjacent 256B output rows = 512B contiguous).

#define GRID_H   64
#define CHANNELS 64

__global__ __launch_bounds__(256, 8)
void proj_trilerp_kernel(const float* __restrict__ img,
                         const float* __restrict__ coords,
                         float* __restrict__ out,
                         int npts)
{
    const int warp = (blockIdx.x * blockDim.x + threadIdx.x) >> 5;
    const int lane = threadIdx.x & 31;
    const int pt   = warp * 2 + (lane >> 4);   // this half-warp's point
    if (pt >= npts) return;

    // Broadcast within each half-warp (2 sectors per load instruction)
    const float x = __ldg(&coords[pt * 3 + 0]) * 0.5f;  // factor = 128/64 = 2
    const float y = __ldg(&coords[pt * 3 + 1]) * 0.5f;
    const float z = __ldg(&coords[pt * 3 + 2]) * 0.5f;

    const float hm1 = (float)(GRID_H - 1);
    const float x1f = floorf(x), x2f = fminf(ceilf(x), hm1);
    const float y1f = floorf(y), y2f = fminf(ceilf(y), hm1);
    const float z1f = floorf(z), z2f = fminf(ceilf(z), hm1);

    // Reference weights: low corner gets (hi - p), high corner gets (p - lo).
    // Degenerate lo==hi case: weights sum to 0, matching the reference.
    const float cx1 = x - x1f, cx0 = x2f - x;
    const float cy1 = y - y1f, cy0 = y2f - y;
    const float cz1 = z - z1f, cz0 = z2f - z;

    const int ix1 = (int)x1f, ix2 = (int)x2f;
    const int iy1 = (int)y1f, iy2 = (int)y2f;
    const int iz1 = (int)z1f, iz2 = (int)z2f;

    const int bx1 = ix1 * (GRID_H * GRID_H * CHANNELS);
    const int bx2 = ix2 * (GRID_H * GRID_H * CHANNELS);
    const int by1 = iy1 * (GRID_H * CHANNELS);
    const int by2 = iy2 * (GRID_H * CHANNELS);
    const int bz1 = iz1 * CHANNELS;
    const int bz2 = iz2 * CHANNELS;

    const int c = (lane & 15) * 4;   // this lane's 4 channels (16B)

    // 8 corner row addresses
    const float4* p000 = (const float4*)(img + bx1 + by1 + bz1 + c);
    const float4* p100 = (const float4*)(img + bx2 + by1 + bz1 + c);
    const float4* p010 = (const float4*)(img + bx1 + by2 + bz1 + c);
    const float4* p110 = (const float4*)(img + bx2 + by2 + bz1 + c);
    const float4* p001 = (const float4*)(img + bx1 + by1 + bz2 + c);
    const float4* p101 = (const float4*)(img + bx2 + by1 + bz2 + c);
    const float4* p011 = (const float4*)(img + bx1 + by2 + bz2 + c);
    const float4* p111 = (const float4*)(img + bx2 + by2 + bz2 + c);

    // Front-batch all 8 wide loads: 8-deep MLP per warp to hide
    // DRAM-class latency (volume only partially L2-resident).
    const float4 q000 = *p000;
    const float4 q100 = *p100;
    const float4 q010 = *p010;
    const float4 q110 = *p110;
    const float4 q001 = *p001;
    const float4 q101 = *p101;
    const float4 q011 = *p011;
    const float4 q111 = *p111;

    // 8 trilinear weights
    const float w000 = cx0 * cy0 * cz0;
    const float w100 = cx1 * cy0 * cz0;
    const float w010 = cx0 * cy1 * cz0;
    const float w110 = cx1 * cy1 * cz0;
    const float w001 = cx0 * cy0 * cz1;
    const float w101 = cx1 * cy0 * cz1;
    const float w011 = cx0 * cy1 * cz1;
    const float w111 = cx1 * cy1 * cz1;

    float ax, ay, az, aw;
    ax = w000 * q000.x;            ay = w000 * q000.y;
    az = w000 * q000.z;            aw = w000 * q000.w;
    ax = fmaf(w100, q100.x, ax);   ay = fmaf(w100, q100.y, ay);
    az = fmaf(w100, q100.z, az);   aw = fmaf(w100, q100.w, aw);
    ax = fmaf(w010, q010.x, ax);   ay = fmaf(w010, q010.y, ay);
    az = fmaf(w010, q010.z, az);   aw = fmaf(w010, q010.w, aw);
    ax = fmaf(w110, q110.x, ax);   ay = fmaf(w110, q110.y, ay);
    az = fmaf(w110, q110.z, az);   aw = fmaf(w110, q110.w, aw);
    ax = fmaf(w001, q001.x, ax);   ay = fmaf(w001, q001.y, ay);
    az = fmaf(w001, q001.z, az);   aw = fmaf(w001, q001.w, aw);
    ax = fmaf(w101, q101.x, ax);   ay = fmaf(w101, q101.y, ay);
    az = fmaf(w101, q101.z, az);   aw = fmaf(w101, q101.w, aw);
    ax = fmaf(w011, q011.x, ax);   ay = fmaf(w011, q011.y, ay);
    az = fmaf(w011, q011.z, az);   aw = fmaf(w011, q011.w, aw);
    ax = fmaf(w111, q111.x, ax);   ay = fmaf(w111, q111.y, ay);
    az = fmaf(w111, q111.z, az);   aw = fmaf(w111, q111.w, aw);

    // Streaming store: output is write-once, keep it from evicting the
    // feature volume out of L2. Full warp stores 512B contiguous.
    float4* o = (float4*)(out + pt * CHANNELS + c);
    __stcs(o, make_float4(ax, ay, az, aw));
}

extern "C" void kernel_launch(void* const* d_in, const int* in_sizes, int n_in,
                              void* d_out, int out_size)
{
    const float* img    = (const float*)d_in[0];   // [1,64,64,64,64]
    const float* coords = (const float*)d_in[1];   // [1,200000,3]
    float* out          = (float*)d_out;           // [1,200000,64]

    const int npts = in_sizes[1] / 3;              // 200000

    // 2 points per warp, 8 warps per block -> 16 points per block
    const int pts_per_block = 16;
    const int blocks = (npts + pts_per_block - 1) / pts_per_block;
    proj_trilerp_kernel<<<blocks, 256>>>(img, coords, out, npts);
}

// round 14
// speedup vs baseline: 1.0568x; 1.0568x over previous
#include <cuda_runtime.h>

// Trilinear interpolation:
//   img:    [64, 64, 64, 64]  (D, H, W, C) fp32, C contiguous
//   coords: [200000, 3] fp32 in [0, 128)  -> scaled by 1/2 into [0, 64)
//   out:    [200000, 64] fp32
//
// Half-warp per point: lanes 0-15 -> point 2w, lanes 16-31 -> point 2w+1.
// Each lane covers 4 channels (float4). 8 corner loads per lane, all
// front-batched (8-deep MLP vs 4 previously), 32 FMAs, no shuffles, one
// dense full-warp STG.128 (2 adjacent 256B output rows = 512B contiguous).

#define GRID_H   64
#define CHANNELS 64

__global__ __launch_bounds__(256, 8)
void proj_trilerp_kernel(const float* __restrict__ img,
                         const float* __restrict__ coords,
                         float* __restrict__ out,
                         int npts)
{
    const int warp = (blockIdx.x * blockDim.x + threadIdx.x) >> 5;
    const int lane = threadIdx.x & 31;
    const int pt   = warp * 2 + (lane >> 4);   // this half-warp's point
    if (pt >= npts) return;

    // Broadcast within each half-warp (2 sectors per load instruction)
    const float x = __ldg(&coords[pt * 3 + 0]) * 0.5f;  // factor = 128/64 = 2
    const float y = __ldg(&coords[pt * 3 + 1]) * 0.5f;
    const float z = __ldg(&coords[pt * 3 + 2]) * 0.5f;

    const float hm1 = (float)(GRID_H - 1);
    const float x1f = floorf(x), x2f = fminf(ceilf(x), hm1);
    const float y1f = floorf(y), y2f = fminf(ceilf(y), hm1);
    const float z1f = floorf(z), z2f = fminf(ceilf(z), hm1);

    // Reference weights: low corner gets (hi - p), high corner gets (p - lo).
    // Degenerate lo==hi case: weights sum to 0, matching the reference.
    const float cx1 = x - x1f, cx0 = x2f - x;
    const float cy1 = y - y1f, cy0 = y2f - y;
    const float cz1 = z - z1f, cz0 = z2f - z;

    const int ix1 = (int)x1f, ix2 = (int)x2f;
    const int iy1 = (int)y1f, iy2 = (int)y2f;
    const int iz1 = (int)z1f, iz2 = (int)z2f;

    const int bx1 = ix1 * (GRID_H * GRID_H * CHANNELS);
    const int bx2 = ix2 * (GRID_H * GRID_H * CHANNELS);
    const int by1 = iy1 * (GRID_H * CHANNELS);
    const int by2 = iy2 * (GRID_H * CHANNELS);
    const int bz1 = iz1 * CHANNELS;
    const int bz2 = iz2 * CHANNELS;

    const int c = (lane & 15) * 4;   // this lane's 4 channels (16B)

    // 8 corner row addresses
    const float4* p000 = (const float4*)(img + bx1 + by1 + bz1 + c);
    const float4* p100 = (const float4*)(img + bx2 + by1 + bz1 + c);
    const float4* p010 = (const float4*)(img + bx1 + by2 + bz1 + c);
    const float4* p110 = (const float4*)(img + bx2 + by2 + bz1 + c);
    const float4* p001 = (const float4*)(img + bx1 + by1 + bz2 + c);
    const float4* p101 = (const float4*)(img + bx2 + by1 + bz2 + c);
    const float4* p011 = (const float4*)(img + bx1 + by2 + bz2 + c);
    const float4* p111 = (const float4*)(img + bx2 + by2 + bz2 + c);

    // Front-batch all 8 wide loads: 8-deep MLP per warp to hide
    // DRAM-class latency (volume only partially L2-resident).
    const float4 q000 = *p000;
    const float4 q100 = *p100;
    const float4 q010 = *p010;
    const float4 q110 = *p110;
    const float4 q001 = *p001;
    const float4 q101 = *p101;
    const float4 q011 = *p011;
    const float4 q111 = *p111;

    // 8 trilinear weights
    const float w000 = cx0 * cy0 * cz0;
    const float w100 = cx1 * cy0 * cz0;
    const float w010 = cx0 * cy1 * cz0;
    const float w110 = cx1 * cy1 * cz0;
    const float w001 = cx0 * cy0 * cz1;
    const float w101 = cx1 * cy0 * cz1;
    const float w011 = cx0 * cy1 * cz1;
    const float w111 = cx1 * cy1 * cz1;

    float ax, ay, az, aw;
    ax = w000 * q000.x;            ay = w000 * q000.y;
    az = w000 * q000.z;            aw = w000 * q000.w;
    ax = fmaf(w100, q100.x, ax);   ay = fmaf(w100, q100.y, ay);
    az = fmaf(w100, q100.z, az);   aw = fmaf(w100, q100.w, aw);
    ax = fmaf(w010, q010.x, ax);   ay = fmaf(w010, q010.y, ay);
    az = fmaf(w010, q010.z, az);   aw = fmaf(w010, q010.w, aw);
    ax = fmaf(w110, q110.x, ax);   ay = fmaf(w110, q110.y, ay);
    az = fmaf(w110, q110.z, az);   aw = fmaf(w110, q110.w, aw);
    ax = fmaf(w001, q001.x, ax);   ay = fmaf(w001, q001.y, ay);
    az = fmaf(w001, q001.z, az);   aw = fmaf(w001, q001.w, aw);
    ax = fmaf(w101, q101.x, ax);   ay = fmaf(w101, q101.y, ay);
    az = fmaf(w101, q101.z, az);   aw = fmaf(w101, q101.w, aw);
    ax = fmaf(w011, q011.x, ax);   ay = fmaf(w011, q011.y, ay);
    az = fmaf(w011, q011.z, az);   aw = fmaf(w011, q011.w, aw);
    ax = fmaf(w111, q111.x, ax);   ay = fmaf(w111, q111.y, ay);
    az = fmaf(w111, q111.z, az);   aw = fmaf(w111, q111.w, aw);

    // Streaming store: output is write-once, keep it from evicting the
    // feature volume out of L2. Full warp stores 512B contiguous.
    float4* o = (float4*)(out + pt * CHANNELS + c);
    __stcs(o, make_float4(ax, ay, az, aw));
}

extern "C" void kernel_launch(void* const* d_in, const int* in_sizes, int n_in,
                              void* d_out, int out_size)
{
    const float* img    = (const float*)d_in[0];   // [1,64,64,64,64]
    const float* coords = (const float*)d_in[1];   // [1,200000,3]
    float* out          = (float*)d_out;           // [1,200000,64]

    const int npts = in_sizes[1] / 3;              // 200000

    // 2 points per warp, 8 warps per block -> 16 points per block
    const int pts_per_block = 16;
    const int blocks = (npts + pts_per_block - 1) / pts_per_block;
    proj_trilerp_kernel<<<blocks, 256>>>(img, coords, out, npts);
}